// round 2
// baseline (speedup 1.0000x reference)
#include <cuda_runtime.h>
#include <cuda_bf16.h>

// FraudQuantumKernel: out[i] = exp(-||x_i - y_i||^2) * net(x_i) * net(y_i)
// net: 9 layers of  z = tanh(z @ W^T + b) * s + t  (2->2), then Linear(2->1).
//
// Design: MUFU-bound (36 MUFU.TANH + 1 EX2 per pair). All ~93 weight scalars
// loaded into registers once per thread; each thread handles PAIRS_PER_THREAD
// pairs to amortize weight loads. float2 coalesced loads of x/y.

#define NLAYERS_TOTAL 9   // input layer + 8 hidden layers
#define PAIRS_PER_THREAD 8
#define TPB 256

__device__ __forceinline__ float fast_tanh(float x) {
    float y;
    asm("tanh.approx.f32 %0, %1;" : "=f"(y) : "f"(x));
    return y;
}

__global__ __launch_bounds__(TPB, 2)
void fraud_kernel(const float2* __restrict__ x,
                  const float2* __restrict__ y,
                  const float* __restrict__ W0,      // [2,2]
                  const float* __restrict__ b0,      // [2]
                  const float* __restrict__ scale0,  // [2]
                  const float* __restrict__ shift0,  // [2]
                  const float* __restrict__ Ws,      // [8,2,2]
                  const float* __restrict__ bs,      // [8,2]
                  const float* __restrict__ scales,  // [8,2]
                  const float* __restrict__ shifts,  // [8,2]
                  const float* __restrict__ Wf,      // [1,2]
                  const float* __restrict__ bf,      // [1]
                  float* __restrict__ out,
                  int n)
{
    // ---- load all layer params into registers (uniform across threads) ----
    float w[NLAYERS_TOTAL * 4];
    float bb[NLAYERS_TOTAL * 2];
    float ss[NLAYERS_TOTAL * 2];
    float tt[NLAYERS_TOTAL * 2];

    #pragma unroll
    for (int k = 0; k < 4; k++) w[k] = __ldg(&W0[k]);
    #pragma unroll
    for (int k = 0; k < 2; k++) {
        bb[k] = __ldg(&b0[k]);
        ss[k] = __ldg(&scale0[k]);
        tt[k] = __ldg(&shift0[k]);
    }
    #pragma unroll
    for (int l = 0; l < 8; l++) {
        #pragma unroll
        for (int k = 0; k < 4; k++) w[(l + 1) * 4 + k] = __ldg(&Ws[l * 4 + k]);
        #pragma unroll
        for (int k = 0; k < 2; k++) {
            bb[(l + 1) * 2 + k] = __ldg(&bs[l * 2 + k]);
            ss[(l + 1) * 2 + k] = __ldg(&scales[l * 2 + k]);
            tt[(l + 1) * 2 + k] = __ldg(&shifts[l * 2 + k]);
        }
    }
    const float wf0 = __ldg(&Wf[0]);
    const float wf1 = __ldg(&Wf[1]);
    const float bfv = __ldg(&bf[0]);

    int i = blockIdx.x * (TPB * PAIRS_PER_THREAD) + threadIdx.x;

    #pragma unroll
    for (int p = 0; p < PAIRS_PER_THREAD; p++, i += TPB) {
        if (i < n) {
            float2 xv = x[i];
            float2 yv = y[i];

            float dx = xv.x - yv.x;
            float dy = xv.y - yv.y;
            float rbf = __expf(-fmaf(dx, dx, dy * dy));   // GAMMA = 1.0

            // evaluate both nets in lockstep (4 independent tanh chains per layer)
            float ax0 = xv.x, ax1 = xv.y;
            float ay0 = yv.x, ay1 = yv.y;

            #pragma unroll
            for (int l = 0; l < NLAYERS_TOTAL; l++) {
                const float w00 = w[l * 4 + 0], w01 = w[l * 4 + 1];
                const float w10 = w[l * 4 + 2], w11 = w[l * 4 + 3];
                const float b0v = bb[l * 2 + 0], b1v = bb[l * 2 + 1];
                const float s0v = ss[l * 2 + 0], s1v = ss[l * 2 + 1];
                const float t0v = tt[l * 2 + 0], t1v = tt[l * 2 + 1];

                float px0 = fmaf(ax0, w00, fmaf(ax1, w01, b0v));
                float px1 = fmaf(ax0, w10, fmaf(ax1, w11, b1v));
                float py0 = fmaf(ay0, w00, fmaf(ay1, w01, b0v));
                float py1 = fmaf(ay0, w10, fmaf(ay1, w11, b1v));

                float hx0 = fast_tanh(px0);
                float hx1 = fast_tanh(px1);
                float hy0 = fast_tanh(py0);
                float hy1 = fast_tanh(py1);

                ax0 = fmaf(hx0, s0v, t0v);
                ax1 = fmaf(hx1, s1v, t1v);
                ay0 = fmaf(hy0, s0v, t0v);
                ay1 = fmaf(hy1, s1v, t1v);
            }

            float fx = fmaf(ax0, wf0, fmaf(ax1, wf1, bfv));
            float fy = fmaf(ay0, wf0, fmaf(ay1, wf1, bfv));

            out[i] = rbf * fx * fy;
        }
    }
}

extern "C" void kernel_launch(void* const* d_in, const int* in_sizes, int n_in,
                              void* d_out, int out_size)
{
    const float2* x      = (const float2*)d_in[0];
    const float2* y      = (const float2*)d_in[1];
    const float*  W0     = (const float*)d_in[2];
    const float*  b0     = (const float*)d_in[3];
    const float*  scale0 = (const float*)d_in[4];
    const float*  shift0 = (const float*)d_in[5];
    const float*  Ws     = (const float*)d_in[6];
    const float*  bs     = (const float*)d_in[7];
    const float*  scales = (const float*)d_in[8];
    const float*  shifts = (const float*)d_in[9];
    const float*  Wf     = (const float*)d_in[10];
    const float*  bf     = (const float*)d_in[11];
    float* out = (float*)d_out;

    int n = in_sizes[0] / 2;   // x has 2N floats
    int per_block = TPB * PAIRS_PER_THREAD;
    int blocks = (n + per_block - 1) / per_block;

    fraud_kernel<<<blocks, TPB>>>(x, y, W0, b0, scale0, shift0,
                                  Ws, bs, scales, shifts, Wf, bf, out, n);
}

// round 4
// speedup vs baseline: 1.7109x; 1.7109x over previous
#include <cuda_runtime.h>
#include <cuda_bf16.h>

// out[i] = exp(-||x_i-y_i||^2) * net(x_i) * net(y_i)
// net: 9x { z = tanh(z@W^T + b) * s + t }  (2->2), then Linear(2->1).
//
// R3: scale/shift folded into next layer's (W,b) -> each layer is just
// z = tanh(A z + c). Folded params live in SMEM (57 floats), layer loop kept
// rolled so only ~8 state regs stay live -> high occupancy. 2 pairs per
// inner body = 8 independent tanh chains = MUFU saturated per-warp.

#define TPB 256

__device__ __forceinline__ float fast_tanh(float x) {
    float y;
    asm("tanh.approx.f32 %0, %1;" : "=f"(y) : "f"(x));
    return y;
}

// scalar fallback for a single pair (tail handling)
__device__ __noinline__ float one_pair(const float* __restrict__ sW,
                                       const float* __restrict__ sC,
                                       const float* __restrict__ sF,
                                       float2 xv, float2 yv)
{
    float dx = xv.x - yv.x, dy = xv.y - yv.y;
    float rbf = __expf(-fmaf(dx, dx, dy * dy));
    float a0 = xv.x, a1 = xv.y, b0 = yv.x, b1 = yv.y;
    #pragma unroll 1
    for (int l = 0; l < 9; l++) {
        float w00 = sW[l*4+0], w01 = sW[l*4+1], w10 = sW[l*4+2], w11 = sW[l*4+3];
        float c0 = sC[l*2+0], c1 = sC[l*2+1];
        float u0 = fmaf(a0, w00, fmaf(a1, w01, c0));
        float u1 = fmaf(a0, w10, fmaf(a1, w11, c1));
        float v0 = fmaf(b0, w00, fmaf(b1, w01, c0));
        float v1 = fmaf(b0, w10, fmaf(b1, w11, c1));
        a0 = fast_tanh(u0); a1 = fast_tanh(u1);
        b0 = fast_tanh(v0); b1 = fast_tanh(v1);
    }
    float fx = fmaf(a0, sF[0], fmaf(a1, sF[1], sF[2]));
    float fy = fmaf(b0, sF[0], fmaf(b1, sF[1], sF[2]));
    return rbf * fx * fy;
}

__global__ __launch_bounds__(TPB, 4)
void fraud_kernel(const float4* __restrict__ x4,
                  const float4* __restrict__ y4,
                  const float* __restrict__ W0,      // [2,2]
                  const float* __restrict__ b0,      // [2]
                  const float* __restrict__ scale0,  // [2]
                  const float* __restrict__ shift0,  // [2]
                  const float* __restrict__ Ws,      // [8,2,2]
                  const float* __restrict__ bs,      // [8,2]
                  const float* __restrict__ scales,  // [8,2]
                  const float* __restrict__ shifts,  // [8,2]
                  const float* __restrict__ Wf,      // [1,2]
                  const float* __restrict__ bf,      // [1]
                  float* __restrict__ out,
                  int n)
{
    __shared__ float sW[9 * 4];   // folded layer weights
    __shared__ float sC[9 * 2];   // folded layer biases
    __shared__ float sF[3];       // folded head: wf0, wf1, bf

    const int tid = threadIdx.x;

    // ---- fold scale/shift of layer l-1 into layer l's (W,b); head folds layer 8's ----
    if (tid < 9) {
        const float* W = (tid == 0) ? W0 : (Ws + (tid - 1) * 4);
        const float* B = (tid == 0) ? b0 : (bs + (tid - 1) * 2);
        float ps0 = 1.f, ps1 = 1.f, pt0 = 0.f, pt1 = 0.f;
        if (tid == 1) {
            ps0 = scale0[0]; ps1 = scale0[1];
            pt0 = shift0[0]; pt1 = shift0[1];
        } else if (tid >= 2) {
            ps0 = scales[(tid - 2) * 2 + 0]; ps1 = scales[(tid - 2) * 2 + 1];
            pt0 = shifts[(tid - 2) * 2 + 0]; pt1 = shifts[(tid - 2) * 2 + 1];
        }
        sW[tid * 4 + 0] = W[0] * ps0;
        sW[tid * 4 + 1] = W[1] * ps1;
        sW[tid * 4 + 2] = W[2] * ps0;
        sW[tid * 4 + 3] = W[3] * ps1;
        sC[tid * 2 + 0] = B[0] + W[0] * pt0 + W[1] * pt1;
        sC[tid * 2 + 1] = B[1] + W[2] * pt0 + W[3] * pt1;
    } else if (tid == 9) {
        float s0 = scales[14], s1 = scales[15];
        float t0 = shifts[14], t1 = shifts[15];
        sF[0] = Wf[0] * s0;
        sF[1] = Wf[1] * s1;
        sF[2] = bf[0] + Wf[0] * t0 + Wf[1] * t1;
    }
    __syncthreads();

    // ---- each thread: 2 groups x 2 pairs (float4 loads = 2 pairs of x or y) ----
    #pragma unroll
    for (int g = 0; g < 2; g++) {
        int f = blockIdx.x * (TPB * 2) + g * TPB + tid;  // float4 index
        int p0 = 2 * f;                                   // first pair index
        if (p0 + 1 < n) {
            float4 xa = x4[f];
            float4 ya = y4[f];

            // RBF factors
            float dxA = xa.x - ya.x, dyA = xa.y - ya.y;
            float dxB = xa.z - ya.z, dyB = xa.w - ya.w;
            float rbfA = __expf(-fmaf(dxA, dxA, dyA * dyA));
            float rbfB = __expf(-fmaf(dxB, dxB, dyB * dyB));

            // 8 chains: pair A nets (a*, b*), pair B nets (c*, d*)
            float a0 = xa.x, a1 = xa.y;   // net(x_A)
            float b0_ = ya.x, b1_ = ya.y; // net(y_A)
            float c0 = xa.z, c1 = xa.w;   // net(x_B)
            float d0 = ya.z, d1 = ya.w;   // net(y_B)

            #pragma unroll 1
            for (int l = 0; l < 9; l++) {
                const float w00 = sW[l*4+0], w01 = sW[l*4+1];
                const float w10 = sW[l*4+2], w11 = sW[l*4+3];
                const float e0 = sC[l*2+0], e1 = sC[l*2+1];

                float ua0 = fmaf(a0,  w00, fmaf(a1,  w01, e0));
                float ua1 = fmaf(a0,  w10, fmaf(a1,  w11, e1));
                float ub0 = fmaf(b0_, w00, fmaf(b1_, w01, e0));
                float ub1 = fmaf(b0_, w10, fmaf(b1_, w11, e1));
                float uc0 = fmaf(c0,  w00, fmaf(c1,  w01, e0));
                float uc1 = fmaf(c0,  w10, fmaf(c1,  w11, e1));
                float ud0 = fmaf(d0,  w00, fmaf(d1,  w01, e0));
                float ud1 = fmaf(d0,  w10, fmaf(d1,  w11, e1));

                a0  = fast_tanh(ua0); a1  = fast_tanh(ua1);
                b0_ = fast_tanh(ub0); b1_ = fast_tanh(ub1);
                c0  = fast_tanh(uc0); c1  = fast_tanh(uc1);
                d0  = fast_tanh(ud0); d1  = fast_tanh(ud1);
            }

            const float wf0 = sF[0], wf1 = sF[1], bfv = sF[2];
            float fxA = fmaf(a0,  wf0, fmaf(a1,  wf1, bfv));
            float fyA = fmaf(b0_, wf0, fmaf(b1_, wf1, bfv));
            float fxB = fmaf(c0,  wf0, fmaf(c1,  wf1, bfv));
            float fyB = fmaf(d0,  wf0, fmaf(d1,  wf1, bfv));

            float2 r;
            r.x = rbfA * fxA * fyA;
            r.y = rbfB * fxB * fyB;
            reinterpret_cast<float2*>(out)[f] = r;
        } else if (p0 < n) {
            // tail: single remaining pair
            const float2* x2 = reinterpret_cast<const float2*>(x4);
            const float2* y2 = reinterpret_cast<const float2*>(y4);
            out[p0] = one_pair(sW, sC, sF, x2[p0], y2[p0]);
        }
    }
}

extern "C" void kernel_launch(void* const* d_in, const int* in_sizes, int n_in,
                              void* d_out, int out_size)
{
    const float4* x4     = (const float4*)d_in[0];
    const float4* y4     = (const float4*)d_in[1];
    const float*  W0     = (const float*)d_in[2];
    const float*  b0     = (const float*)d_in[3];
    const float*  scale0 = (const float*)d_in[4];
    const float*  shift0 = (const float*)d_in[5];
    const float*  Ws     = (const float*)d_in[6];
    const float*  bs     = (const float*)d_in[7];
    const float*  scales = (const float*)d_in[8];
    const float*  shifts = (const float*)d_in[9];
    const float*  Wf     = (const float*)d_in[10];
    const float*  bf     = (const float*)d_in[11];
    float* out = (float*)d_out;

    int n = in_sizes[0] / 2;            // pairs
    int per_block = TPB * 4;            // 4 pairs per thread
    int blocks = (n + per_block - 1) / per_block;

    fraud_kernel<<<blocks, TPB>>>(x4, y4, W0, b0, scale0, shift0,
                                  Ws, bs, scales, shifts, Wf, bf, out, n);
}